// round 4
// baseline (speedup 1.0000x reference)
#include <cuda_runtime.h>
#include <math.h>

#define NN 50000
#define NE 800000

// ---- device scratch ----
__device__ float4 g_h[NN * 16];     // h = x@W, [NN,64] as float4
__device__ float  g_s1[NN];         // dot(h[n], a[:64])
__device__ float  g_s2[NN];         // dot(h[n], a[64:])
__device__ float  g_expv[NE];       // exp(leaky(logit)) per edge
__device__ int    g_cnt[NN];        // in-degree
__device__ int    g_off[NN];        // exclusive prefix (CSR row start)
__device__ int    g_cur[NN];        // running cursor for sort
__device__ int2   g_srt[NE];        // sorted records: (src node j, expv bits)
__device__ float  g_sum;            // sum of exp(logits)

// ---------------- K0: zero counters + sum ----------------
__global__ void k_zero() {
    int idx = blockIdx.x * blockDim.x + threadIdx.x;
    if (idx < NN) g_cnt[idx] = 0;
    if (idx == 0) g_sum = 0.f;
}

// ---------------- K1: h = x@W + per-node scores (f32x2 packed FMA) ----------------
#define NPB 338   // 148*338 = 50024 >= NN
__global__ void __launch_bounds__(256, 1)
k_gemm(const float* __restrict__ x,
       const float* __restrict__ W,
       const float* __restrict__ attn) {
    __shared__ ulonglong2 Ws2[128 * 16];
    __shared__ float aws[128];
    const int t = threadIdx.x;
    {
        const float4* W4 = (const float4*)W;
        float4* Ws4 = (float4*)Ws2;
        for (int i = t; i < 2048; i += 256) Ws4[i] = W4[i];
        if (t < 128) aws[t] = attn[t];
    }
    __syncthreads();

    const int base = blockIdx.x * NPB;
    const int n0 = base + 2 * t;
    if (2 * t >= NPB || n0 >= NN) return;
    const int n1 = n0 + 1;
    const size_t r0 = (size_t)n0;
    const size_t r1 = (size_t)((n1 < NN) ? n1 : n0);

    unsigned long long accA[32], accB[32];
    #pragma unroll
    for (int c = 0; c < 32; c++) { accA[c] = 0ull; accB[c] = 0ull; }

    const float4* x4 = (const float4*)x;
    #pragma unroll 1
    for (int k4 = 0; k4 < 32; k4++) {
        float4 xa = x4[r0 * 32 + k4];
        float4 xb = x4[r1 * 32 + k4];
        #pragma unroll
        for (int s = 0; s < 4; s++) {
            float fa = (s == 0) ? xa.x : (s == 1) ? xa.y : (s == 2) ? xa.z : xa.w;
            float fb = (s == 0) ? xb.x : (s == 1) ? xb.y : (s == 2) ? xb.z : xb.w;
            unsigned long long pa, pb;
            asm("mov.b64 %0, {%1, %1};" : "=l"(pa) : "f"(fa));
            asm("mov.b64 %0, {%1, %1};" : "=l"(pb) : "f"(fb));
            const ulonglong2* wk = Ws2 + (k4 * 4 + s) * 16;
            #pragma unroll
            for (int c = 0; c < 16; c++) {
                ulonglong2 wv = wk[c];
                asm("fma.rn.f32x2 %0, %1, %2, %0;" : "+l"(accA[2*c])   : "l"(pa), "l"(wv.x));
                asm("fma.rn.f32x2 %0, %1, %2, %0;" : "+l"(accA[2*c+1]) : "l"(pa), "l"(wv.y));
                asm("fma.rn.f32x2 %0, %1, %2, %0;" : "+l"(accB[2*c])   : "l"(pb), "l"(wv.x));
                asm("fma.rn.f32x2 %0, %1, %2, %0;" : "+l"(accB[2*c+1]) : "l"(pb), "l"(wv.y));
            }
        }
    }

    {
        float s1 = 0.f, s2 = 0.f;
        #pragma unroll
        for (int q = 0; q < 16; q++) {
            float4 v;
            asm("mov.b64 {%0, %1}, %2;" : "=f"(v.x), "=f"(v.y) : "l"(accA[2*q]));
            asm("mov.b64 {%0, %1}, %2;" : "=f"(v.z), "=f"(v.w) : "l"(accA[2*q+1]));
            g_h[r0 * 16 + q] = v;
            s1 += v.x*aws[4*q] + v.y*aws[4*q+1] + v.z*aws[4*q+2] + v.w*aws[4*q+3];
            s2 += v.x*aws[64+4*q] + v.y*aws[64+4*q+1] + v.z*aws[64+4*q+2] + v.w*aws[64+4*q+3];
        }
        g_s1[n0] = s1; g_s2[n0] = s2;
    }
    if (n1 < NN) {
        float s1 = 0.f, s2 = 0.f;
        #pragma unroll
        for (int q = 0; q < 16; q++) {
            float4 v;
            asm("mov.b64 {%0, %1}, %2;" : "=f"(v.x), "=f"(v.y) : "l"(accB[2*q]));
            asm("mov.b64 {%0, %1}, %2;" : "=f"(v.z), "=f"(v.w) : "l"(accB[2*q+1]));
            g_h[(size_t)n1 * 16 + q] = v;
            s1 += v.x*aws[4*q] + v.y*aws[4*q+1] + v.z*aws[4*q+2] + v.w*aws[4*q+3];
            s2 += v.x*aws[64+4*q] + v.y*aws[64+4*q+1] + v.z*aws[64+4*q+2] + v.w*aws[64+4*q+3];
        }
        g_s1[n1] = s1; g_s2[n1] = s2;
    }
}

// ---------------- K2: per-edge expv + degree histogram + global sum ----------------
__global__ void k_pre(const int* __restrict__ eidx) {
    int e = blockIdx.x * blockDim.x + threadIdx.x;
    float v = 0.f;
    if (e < NE) {
        int i = __ldg(eidx + e);
        int j = __ldg(eidx + NE + e);
        float l = g_s1[i] + g_s2[j];
        l = (l > 0.f) ? l : 0.2f * l;    // leaky_relu 0.2
        float ex = __expf(l);
        g_expv[e] = ex;
        v = ex;
        atomicAdd(&g_cnt[i], 1);
    }
    #pragma unroll
    for (int o = 16; o > 0; o >>= 1) v += __shfl_down_sync(0xffffffffu, v, o);
    __shared__ float wr[8];
    int w = threadIdx.x >> 5, lane = threadIdx.x & 31;
    if (lane == 0) wr[w] = v;
    __syncthreads();
    if (w == 0) {
        float s = (lane < 8) ? wr[lane] : 0.f;
        #pragma unroll
        for (int o = 4; o > 0; o >>= 1) s += __shfl_down_sync(0xffffffffu, s, o);
        if (lane == 0) atomicAdd(&g_sum, s);
    }
}

// ---------------- K3: exclusive scan of counts (single block) ----------------
#define SCAN_T 1024
#define CHUNK  49   // 1024*49 = 50176 >= NN
__global__ void __launch_bounds__(SCAN_T)
k_scan() {
    __shared__ int part[SCAN_T];
    int t = threadIdx.x;
    int beg = t * CHUNK;
    int end = min(beg + CHUNK, NN);
    int s = 0;
    for (int i = beg; i < end; i++) s += g_cnt[i];
    part[t] = s;
    __syncthreads();
    #pragma unroll
    for (int off = 1; off < SCAN_T; off <<= 1) {
        int add = (t >= off) ? part[t - off] : 0;
        __syncthreads();
        part[t] += add;
        __syncthreads();
    }
    int run = part[t] - s;   // exclusive base for this chunk
    for (int i = beg; i < end; i++) {
        g_off[i] = run;
        g_cur[i] = run;
        run += g_cnt[i];
    }
}

// ---------------- K4: counting-sort edges by destination ----------------
__global__ void k_sort(const int* __restrict__ eidx) {
    int e = blockIdx.x * blockDim.x + threadIdx.x;
    if (e >= NE) return;
    int i = __ldg(eidx + e);
    int j = __ldg(eidx + NE + e);
    int pos = atomicAdd(&g_cur[i], 1);
    g_srt[pos] = make_int2(j, __float_as_int(g_expv[e]));
}

// ---------------- K5: per-node gather + normalize + tiled 8-head output ----------------
// warp handles 2 nodes, 16 lanes/node, one float4 column chunk per lane.
__global__ void k_gather(float* __restrict__ out) {
    int gt = blockIdx.x * blockDim.x + threadIdx.x;
    int lane = threadIdx.x & 31;
    int warp = gt >> 5;
    int n = warp * 2 + (lane >> 4);
    if (n >= NN) return;
    int l16 = lane & 15;

    float inv = 1.0f / g_sum;
    int beg = g_off[n];
    int cnt = g_cnt[n];

    float4 acc = make_float4(0.f, 0.f, 0.f, 0.f);
    for (int k = 0; k < cnt; k++) {
        int2 rec = __ldg(&g_srt[beg + k]);          // broadcast across 16 lanes
        float ex = __int_as_float(rec.y);
        float4 hv = g_h[(size_t)rec.x * 16 + l16];
        acc.x += hv.x * ex; acc.y += hv.y * ex;
        acc.z += hv.z * ex; acc.w += hv.w * ex;
    }
    acc.x *= inv; acc.y *= inv; acc.z *= inv; acc.w *= inv;

    float4* o = (float4*)out + (size_t)n * 128;     // 512 floats/row
    #pragma unroll
    for (int hh = 0; hh < 8; hh++) o[hh * 16 + l16] = acc;
}

extern "C" void kernel_launch(void* const* d_in, const int* in_sizes, int n_in,
                              void* d_out, int out_size) {
    const float* x    = (const float*)d_in[0];
    const int*   eidx = (const int*)d_in[1];
    const float* W    = (const float*)d_in[2];
    const float* attn = (const float*)d_in[3];
    float* out = (float*)d_out;

    k_zero<<<(NN + 255) / 256, 256>>>();
    k_gemm<<<148, 256>>>(x, W, attn);
    k_pre<<<(NE + 255) / 256, 256>>>(eidx);
    k_scan<<<1, SCAN_T>>>();
    k_sort<<<(NE + 255) / 256, 256>>>(eidx);
    // NN/2 warps -> NN/2*32 threads
    k_gather<<<(NN / 2 * 32 + 255) / 256, 256>>>(out);
}

// round 5
// speedup vs baseline: 1.6663x; 1.6663x over previous
#include <cuda_runtime.h>
#include <math.h>

#define NN 50000
#define NE 800000
#define SNB 196          // scan blocks: 196*256 = 50176 >= NN

// ---- device scratch ----
__device__ float4 g_h[NN * 16];     // h = x@W, [NN,64] as float4
__device__ float  g_s1[NN];         // dot(h[n], a[:64])
__device__ float  g_s2[NN];         // dot(h[n], a[64:])
__device__ float  g_expv[NE];       // exp(leaky(logit)) per edge
__device__ int    g_cnt[NN];        // in-degree
__device__ int    g_off[NN];        // exclusive prefix (CSR row start)
__device__ int    g_cur[NN];        // running cursor for sort
__device__ int2   g_srt[NE];        // sorted records: (src node j, expv bits)
__device__ int    g_bsum[256];      // per-scan-block sums
__device__ int    g_bbase[256];     // exclusive scan of block sums
__device__ float  g_sum;            // sum of exp(logits)

// ---------------- K0: zero counters + sum ----------------
__global__ void k_zero() {
    int idx = blockIdx.x * blockDim.x + threadIdx.x;
    if (idx < NN) g_cnt[idx] = 0;
    if (idx == 0) g_sum = 0.f;
}

// ---------------- K1: h = x@W + per-node scores (f32x2 packed FMA) ----------------
#define NPB 338   // 148*338 = 50024 >= NN
__global__ void __launch_bounds__(256, 1)
k_gemm(const float* __restrict__ x,
       const float* __restrict__ W,
       const float* __restrict__ attn) {
    __shared__ ulonglong2 Ws2[128 * 16];
    __shared__ float aws[128];
    const int t = threadIdx.x;
    {
        const float4* W4 = (const float4*)W;
        float4* Ws4 = (float4*)Ws2;
        for (int i = t; i < 2048; i += 256) Ws4[i] = W4[i];
        if (t < 128) aws[t] = attn[t];
    }
    __syncthreads();

    const int base = blockIdx.x * NPB;
    const int n0 = base + 2 * t;
    if (2 * t >= NPB || n0 >= NN) return;
    const int n1 = n0 + 1;
    const size_t r0 = (size_t)n0;
    const size_t r1 = (size_t)((n1 < NN) ? n1 : n0);

    unsigned long long accA[32], accB[32];
    #pragma unroll
    for (int c = 0; c < 32; c++) { accA[c] = 0ull; accB[c] = 0ull; }

    const float4* x4 = (const float4*)x;
    #pragma unroll 1
    for (int k4 = 0; k4 < 32; k4++) {
        float4 xa = x4[r0 * 32 + k4];
        float4 xb = x4[r1 * 32 + k4];
        #pragma unroll
        for (int s = 0; s < 4; s++) {
            float fa = (s == 0) ? xa.x : (s == 1) ? xa.y : (s == 2) ? xa.z : xa.w;
            float fb = (s == 0) ? xb.x : (s == 1) ? xb.y : (s == 2) ? xb.z : xb.w;
            unsigned long long pa, pb;
            asm("mov.b64 %0, {%1, %1};" : "=l"(pa) : "f"(fa));
            asm("mov.b64 %0, {%1, %1};" : "=l"(pb) : "f"(fb));
            const ulonglong2* wk = Ws2 + (k4 * 4 + s) * 16;
            #pragma unroll
            for (int c = 0; c < 16; c++) {
                ulonglong2 wv = wk[c];
                asm("fma.rn.f32x2 %0, %1, %2, %0;" : "+l"(accA[2*c])   : "l"(pa), "l"(wv.x));
                asm("fma.rn.f32x2 %0, %1, %2, %0;" : "+l"(accA[2*c+1]) : "l"(pa), "l"(wv.y));
                asm("fma.rn.f32x2 %0, %1, %2, %0;" : "+l"(accB[2*c])   : "l"(pb), "l"(wv.x));
                asm("fma.rn.f32x2 %0, %1, %2, %0;" : "+l"(accB[2*c+1]) : "l"(pb), "l"(wv.y));
            }
        }
    }

    {
        float s1 = 0.f, s2 = 0.f;
        #pragma unroll
        for (int q = 0; q < 16; q++) {
            float4 v;
            asm("mov.b64 {%0, %1}, %2;" : "=f"(v.x), "=f"(v.y) : "l"(accA[2*q]));
            asm("mov.b64 {%0, %1}, %2;" : "=f"(v.z), "=f"(v.w) : "l"(accA[2*q+1]));
            g_h[r0 * 16 + q] = v;
            s1 += v.x*aws[4*q] + v.y*aws[4*q+1] + v.z*aws[4*q+2] + v.w*aws[4*q+3];
            s2 += v.x*aws[64+4*q] + v.y*aws[64+4*q+1] + v.z*aws[64+4*q+2] + v.w*aws[64+4*q+3];
        }
        g_s1[n0] = s1; g_s2[n0] = s2;
    }
    if (n1 < NN) {
        float s1 = 0.f, s2 = 0.f;
        #pragma unroll
        for (int q = 0; q < 16; q++) {
            float4 v;
            asm("mov.b64 {%0, %1}, %2;" : "=f"(v.x), "=f"(v.y) : "l"(accB[2*q]));
            asm("mov.b64 {%0, %1}, %2;" : "=f"(v.z), "=f"(v.w) : "l"(accB[2*q+1]));
            g_h[(size_t)n1 * 16 + q] = v;
            s1 += v.x*aws[4*q] + v.y*aws[4*q+1] + v.z*aws[4*q+2] + v.w*aws[4*q+3];
            s2 += v.x*aws[64+4*q] + v.y*aws[64+4*q+1] + v.z*aws[64+4*q+2] + v.w*aws[64+4*q+3];
        }
        g_s1[n1] = s1; g_s2[n1] = s2;
    }
}

// ---------------- K2: per-edge expv + degree histogram + global sum ----------------
__global__ void k_pre(const int* __restrict__ eidx) {
    int e = blockIdx.x * blockDim.x + threadIdx.x;
    float v = 0.f;
    if (e < NE) {
        int i = __ldg(eidx + e);
        int j = __ldg(eidx + NE + e);
        float l = g_s1[i] + g_s2[j];
        l = (l > 0.f) ? l : 0.2f * l;    // leaky_relu 0.2
        float ex = __expf(l);
        g_expv[e] = ex;
        v = ex;
        atomicAdd(&g_cnt[i], 1);
    }
    #pragma unroll
    for (int o = 16; o > 0; o >>= 1) v += __shfl_down_sync(0xffffffffu, v, o);
    __shared__ float wr[8];
    int w = threadIdx.x >> 5, lane = threadIdx.x & 31;
    if (lane == 0) wr[w] = v;
    __syncthreads();
    if (w == 0) {
        float s = (lane < 8) ? wr[lane] : 0.f;
        #pragma unroll
        for (int o = 4; o > 0; o >>= 1) s += __shfl_down_sync(0xffffffffu, s, o);
        if (lane == 0) atomicAdd(&g_sum, s);
    }
}

// ---------------- K3a: per-block sums of counts ----------------
__global__ void k_scanA() {
    __shared__ int wr[8];
    int b = blockIdx.x;
    int t = threadIdx.x;
    int n = b * 256 + t;
    int v = (n < NN) ? g_cnt[n] : 0;
    #pragma unroll
    for (int o = 16; o > 0; o >>= 1) v += __shfl_down_sync(0xffffffffu, v, o);
    int w = t >> 5, lane = t & 31;
    if (lane == 0) wr[w] = v;
    __syncthreads();
    if (w == 0) {
        int s = (lane < 8) ? wr[lane] : 0;
        #pragma unroll
        for (int o = 4; o > 0; o >>= 1) s += __shfl_down_sync(0xffffffffu, s, o);
        if (lane == 0) g_bsum[b] = s;
    }
}

// ---------------- K3b: exclusive scan of 196 block sums (1 block, smem) ----------------
__global__ void __launch_bounds__(256)
k_scanB() {
    __shared__ int sm[256];
    int t = threadIdx.x;
    int v = (t < SNB) ? g_bsum[t] : 0;
    sm[t] = v;
    __syncthreads();
    #pragma unroll
    for (int off = 1; off < 256; off <<= 1) {
        int add = (t >= off) ? sm[t - off] : 0;
        __syncthreads();
        sm[t] += add;
        __syncthreads();
    }
    if (t < SNB) g_bbase[t] = sm[t] - v;   // exclusive
}

// ---------------- K3c: per-block exclusive scan + base -> offsets ----------------
__global__ void __launch_bounds__(256)
k_scanC() {
    __shared__ int sm[256];
    int b = blockIdx.x;
    int t = threadIdx.x;
    int n = b * 256 + t;
    int v = (n < NN) ? g_cnt[n] : 0;
    sm[t] = v;
    __syncthreads();
    #pragma unroll
    for (int off = 1; off < 256; off <<= 1) {
        int add = (t >= off) ? sm[t - off] : 0;
        __syncthreads();
        sm[t] += add;
        __syncthreads();
    }
    if (n < NN) {
        int o = g_bbase[b] + sm[t] - v;    // exclusive within-chip offset
        g_off[n] = o;
        g_cur[n] = o;
    }
}

// ---------------- K4: counting-sort edges by destination ----------------
__global__ void k_sort(const int* __restrict__ eidx) {
    int e = blockIdx.x * blockDim.x + threadIdx.x;
    if (e >= NE) return;
    int i = __ldg(eidx + e);
    int j = __ldg(eidx + NE + e);
    int pos = atomicAdd(&g_cur[i], 1);
    g_srt[pos] = make_int2(j, __float_as_int(g_expv[e]));
}

// ---------------- K5: per-node gather + normalize + tiled 8-head output ----------------
__global__ void k_gather(float* __restrict__ out) {
    int gt = blockIdx.x * blockDim.x + threadIdx.x;
    int lane = threadIdx.x & 31;
    int warp = gt >> 5;
    int n = warp * 2 + (lane >> 4);
    if (n >= NN) return;
    int l16 = lane & 15;

    float inv = 1.0f / g_sum;
    int beg = g_off[n];
    int cnt = g_cnt[n];

    float4 acc = make_float4(0.f, 0.f, 0.f, 0.f);
    for (int k = 0; k < cnt; k++) {
        int2 rec = __ldg(&g_srt[beg + k]);          // broadcast across 16 lanes
        float ex = __int_as_float(rec.y);
        float4 hv = g_h[(size_t)rec.x * 16 + l16];
        acc.x += hv.x * ex; acc.y += hv.y * ex;
        acc.z += hv.z * ex; acc.w += hv.w * ex;
    }
    acc.x *= inv; acc.y *= inv; acc.z *= inv; acc.w *= inv;

    float4* o = (float4*)out + (size_t)n * 128;     // 512 floats/row
    #pragma unroll
    for (int hh = 0; hh < 8; hh++) o[hh * 16 + l16] = acc;
}

extern "C" void kernel_launch(void* const* d_in, const int* in_sizes, int n_in,
                              void* d_out, int out_size) {
    const float* x    = (const float*)d_in[0];
    const int*   eidx = (const int*)d_in[1];
    const float* W    = (const float*)d_in[2];
    const float* attn = (const float*)d_in[3];
    float* out = (float*)d_out;

    k_zero<<<(NN + 255) / 256, 256>>>();
    k_gemm<<<148, 256>>>(x, W, attn);
    k_pre<<<(NE + 255) / 256, 256>>>(eidx);
    k_scanA<<<SNB, 256>>>();
    k_scanB<<<1, 256>>>();
    k_scanC<<<SNB, 256>>>();
    k_sort<<<(NE + 255) / 256, 256>>>(eidx);
    k_gather<<<(NN / 2 * 32 + 255) / 256, 256>>>(out);
}

// round 7
// speedup vs baseline: 1.7331x; 1.0401x over previous
#include <cuda_runtime.h>
#include <math.h>

#define NN 50000
#define NE 800000
#define SNB 196          // scan blocks: 196*256 = 50176 >= NN

// ---- device scratch ----
__device__ float4 g_h[NN * 16];     // h = x@W, [NN,64] as float4
__device__ float  g_s1[NN];         // dot(h[n], a[:64])
__device__ float  g_s2[NN];         // dot(h[n], a[64:])
__device__ int    g_cnt[NN];        // in-degree
__device__ int    g_off[NN];        // exclusive prefix (CSR row start)
__device__ int    g_cur[NN];        // running cursor for sort
__device__ int2   g_srt[NE];        // sorted records: (src node j, expv bits)
__device__ int    g_bsum[256];      // per-scan-block sums
__device__ int    g_bbase[256];     // exclusive scan of block sums
__device__ float  g_sum;            // sum of exp(logits)

// ---------------- K0: zero counters + sum ----------------
__global__ void k_zero() {
    int idx = blockIdx.x * blockDim.x + threadIdx.x;
    if (idx < NN) g_cnt[idx] = 0;
    if (idx == 0) g_sum = 0.f;
}

// ---------------- K1: destination histogram (reads only ei row) ----------------
__global__ void k_count(const int* __restrict__ eidx) {
    int e = blockIdx.x * blockDim.x + threadIdx.x;
    if (e < NE) atomicAdd(&g_cnt[__ldg(eidx + e)], 1);
}

// ---------------- K2a/b/c: parallel exclusive scan of counts ----------------
__global__ void k_scanA() {
    __shared__ int wr[8];
    int b = blockIdx.x, t = threadIdx.x;
    int n = b * 256 + t;
    int v = (n < NN) ? g_cnt[n] : 0;
    #pragma unroll
    for (int o = 16; o > 0; o >>= 1) v += __shfl_down_sync(0xffffffffu, v, o);
    int w = t >> 5, lane = t & 31;
    if (lane == 0) wr[w] = v;
    __syncthreads();
    if (w == 0) {
        int s = (lane < 8) ? wr[lane] : 0;
        #pragma unroll
        for (int o = 4; o > 0; o >>= 1) s += __shfl_down_sync(0xffffffffu, s, o);
        if (lane == 0) g_bsum[b] = s;
    }
}

__global__ void __launch_bounds__(256)
k_scanB() {
    __shared__ int sm[256];
    int t = threadIdx.x;
    int v = (t < SNB) ? g_bsum[t] : 0;
    sm[t] = v;
    __syncthreads();
    #pragma unroll
    for (int off = 1; off < 256; off <<= 1) {
        int add = (t >= off) ? sm[t - off] : 0;
        __syncthreads();
        sm[t] += add;
        __syncthreads();
    }
    if (t < SNB) g_bbase[t] = sm[t] - v;
}

__global__ void __launch_bounds__(256)
k_scanC() {
    __shared__ int sm[256];
    int b = blockIdx.x, t = threadIdx.x;
    int n = b * 256 + t;
    int v = (n < NN) ? g_cnt[n] : 0;
    sm[t] = v;
    __syncthreads();
    #pragma unroll
    for (int off = 1; off < 256; off <<= 1) {
        int add = (t >= off) ? sm[t - off] : 0;
        __syncthreads();
        sm[t] += add;
        __syncthreads();
    }
    if (n < NN) {
        int o = g_bbase[b] + sm[t] - v;
        g_off[n] = o;
        g_cur[n] = o;
    }
}

// ---------------- K3: h = x@W + per-node scores (f32x2 packed FMA) ----------------
#define NPB 338   // 148*338 = 50024 >= NN
__global__ void __launch_bounds__(256, 1)
k_gemm(const float* __restrict__ x,
       const float* __restrict__ W,
       const float* __restrict__ attn) {
    __shared__ ulonglong2 Ws2[128 * 16];
    __shared__ float aws[128];
    const int t = threadIdx.x;
    {
        const float4* W4 = (const float4*)W;
        float4* Ws4 = (float4*)Ws2;
        for (int i = t; i < 2048; i += 256) Ws4[i] = W4[i];
        if (t < 128) aws[t] = attn[t];
    }
    __syncthreads();

    const int base = blockIdx.x * NPB;
    const int n0 = base + 2 * t;
    if (2 * t >= NPB || n0 >= NN) return;
    const int n1 = n0 + 1;
    const size_t r0 = (size_t)n0;
    const size_t r1 = (size_t)((n1 < NN) ? n1 : n0);

    unsigned long long accA[32], accB[32];
    #pragma unroll
    for (int c = 0; c < 32; c++) { accA[c] = 0ull; accB[c] = 0ull; }

    const float4* x4 = (const float4*)x;
    #pragma unroll 1
    for (int k4 = 0; k4 < 32; k4++) {
        float4 xa = x4[r0 * 32 + k4];
        float4 xb = x4[r1 * 32 + k4];
        #pragma unroll
        for (int s = 0; s < 4; s++) {
            float fa = (s == 0) ? xa.x : (s == 1) ? xa.y : (s == 2) ? xa.z : xa.w;
            float fb = (s == 0) ? xb.x : (s == 1) ? xb.y : (s == 2) ? xb.z : xb.w;
            unsigned long long pa, pb;
            asm("mov.b64 %0, {%1, %1};" : "=l"(pa) : "f"(fa));
            asm("mov.b64 %0, {%1, %1};" : "=l"(pb) : "f"(fb));
            const ulonglong2* wk = Ws2 + (k4 * 4 + s) * 16;
            #pragma unroll
            for (int c = 0; c < 16; c++) {
                ulonglong2 wv = wk[c];
                asm("fma.rn.f32x2 %0, %1, %2, %0;" : "+l"(accA[2*c])   : "l"(pa), "l"(wv.x));
                asm("fma.rn.f32x2 %0, %1, %2, %0;" : "+l"(accA[2*c+1]) : "l"(pa), "l"(wv.y));
                asm("fma.rn.f32x2 %0, %1, %2, %0;" : "+l"(accB[2*c])   : "l"(pb), "l"(wv.x));
                asm("fma.rn.f32x2 %0, %1, %2, %0;" : "+l"(accB[2*c+1]) : "l"(pb), "l"(wv.y));
            }
        }
    }

    {
        float s1 = 0.f, s2 = 0.f;
        #pragma unroll
        for (int q = 0; q < 16; q++) {
            float4 v;
            asm("mov.b64 {%0, %1}, %2;" : "=f"(v.x), "=f"(v.y) : "l"(accA[2*q]));
            asm("mov.b64 {%0, %1}, %2;" : "=f"(v.z), "=f"(v.w) : "l"(accA[2*q+1]));
            g_h[r0 * 16 + q] = v;
            s1 += v.x*aws[4*q] + v.y*aws[4*q+1] + v.z*aws[4*q+2] + v.w*aws[4*q+3];
            s2 += v.x*aws[64+4*q] + v.y*aws[64+4*q+1] + v.z*aws[64+4*q+2] + v.w*aws[64+4*q+3];
        }
        g_s1[n0] = s1; g_s2[n0] = s2;
    }
    if (n1 < NN) {
        float s1 = 0.f, s2 = 0.f;
        #pragma unroll
        for (int q = 0; q < 16; q++) {
            float4 v;
            asm("mov.b64 {%0, %1}, %2;" : "=f"(v.x), "=f"(v.y) : "l"(accB[2*q]));
            asm("mov.b64 {%0, %1}, %2;" : "=f"(v.z), "=f"(v.w) : "l"(accB[2*q+1]));
            g_h[(size_t)n1 * 16 + q] = v;
            s1 += v.x*aws[4*q] + v.y*aws[4*q+1] + v.z*aws[4*q+2] + v.w*aws[4*q+3];
            s2 += v.x*aws[64+4*q] + v.y*aws[64+4*q+1] + v.z*aws[64+4*q+2] + v.w*aws[64+4*q+3];
        }
        g_s1[n1] = s1; g_s2[n1] = s2;
    }
}

// ---------------- K4: fused expv + counting-sort + global sum ----------------
__global__ void k_sort(const int* __restrict__ eidx) {
    int e = blockIdx.x * blockDim.x + threadIdx.x;
    float v = 0.f;
    if (e < NE) {
        int i = __ldg(eidx + e);
        int j = __ldg(eidx + NE + e);
        float l = g_s1[i] + g_s2[j];
        l = (l > 0.f) ? l : 0.2f * l;    // leaky_relu 0.2
        float ex = __expf(l);
        v = ex;
        int pos = atomicAdd(&g_cur[i], 1);
        g_srt[pos] = make_int2(j, __float_as_int(ex));
    }
    #pragma unroll
    for (int o = 16; o > 0; o >>= 1) v += __shfl_down_sync(0xffffffffu, v, o);
    __shared__ float wr[8];
    int w = threadIdx.x >> 5, lane = threadIdx.x & 31;
    if (lane == 0) wr[w] = v;
    __syncthreads();
    if (w == 0) {
        float s = (lane < 8) ? wr[lane] : 0.f;
        #pragma unroll
        for (int o = 4; o > 0; o >>= 1) s += __shfl_down_sync(0xffffffffu, s, o);
        if (lane == 0) atomicAdd(&g_sum, s);
    }
}

// ---------------- K5: per-node gather (1 warp/node, 2 records in flight) ----------------
__global__ void k_gather(float* __restrict__ out) {
    int gt = blockIdx.x * blockDim.x + threadIdx.x;
    int lane = threadIdx.x & 31;
    int n = gt >> 5;                    // one warp per node
    if (n >= NN) return;
    int l16 = lane & 15;
    int sub = lane >> 4;                // 0: even records, 1: odd records

    float inv = 1.0f / g_sum;
    int beg = g_off[n];
    int cnt = g_cnt[n];

    float4 acc = make_float4(0.f, 0.f, 0.f, 0.f);
    int k = sub;
    int2 rec = (k < cnt) ? __ldg(&g_srt[beg + k]) : make_int2(0, 0);
    while (k < cnt) {
        int2 cur = rec;
        int kn = k + 2;
        if (kn < cnt) rec = __ldg(&g_srt[beg + kn]);   // prefetch next
        float ex = __int_as_float(cur.y);
        float4 hv = g_h[(size_t)cur.x * 16 + l16];
        acc.x += hv.x * ex; acc.y += hv.y * ex;
        acc.z += hv.z * ex; acc.w += hv.w * ex;
        k = kn;
    }
    // merge even/odd halves (lanes l and l^16 hold partial sums for same column)
    acc.x += __shfl_xor_sync(0xffffffffu, acc.x, 16);
    acc.y += __shfl_xor_sync(0xffffffffu, acc.y, 16);
    acc.z += __shfl_xor_sync(0xffffffffu, acc.z, 16);
    acc.w += __shfl_xor_sync(0xffffffffu, acc.w, 16);
    acc.x *= inv; acc.y *= inv; acc.z *= inv; acc.w *= inv;

    // write 8-head tiled row with all 32 lanes: float4 index f = lane + 32*q,
    // column = f & 15 == l16 for all q  -> value is this lane's acc.
    float4* o = (float4*)out + (size_t)n * 128;
    #pragma unroll
    for (int q = 0; q < 4; q++) o[lane + 32 * q] = acc;
}

extern "C" void kernel_launch(void* const* d_in, const int* in_sizes, int n_in,
                              void* d_out, int out_size) {
    const float* x    = (const float*)d_in[0];
    const int*   eidx = (const int*)d_in[1];
    const float* W    = (const float*)d_in[2];
    const float* attn = (const float*)d_in[3];
    float* out = (float*)d_out;

    k_zero<<<(NN + 255) / 256, 256>>>();
    k_count<<<(NE + 255) / 256, 256>>>(eidx);
    k_scanA<<<SNB, 256>>>();
    k_scanB<<<1, 256>>>();
    k_scanC<<<SNB, 256>>>();
    k_gemm<<<148, 256>>>(x, W, attn);
    k_sort<<<(NE + 255) / 256, 256>>>(eidx);
    // one warp per node
    k_gather<<<(NN * 32 + 255) / 256, 256>>>(out);
}